// round 12
// baseline (speedup 1.0000x reference)
#include <cuda_runtime.h>
#include <cuda_fp16.h>
#include <cstdint>

#define NLAB 16
#define DIM  256
#define HID  128
#define BATCH 32
#define SEQ  2048
#define G3   384
#define NPAIR 32
#define BC   8
#define NSTAGE 8
#define GIP  392
#define ST1  32768          // phase-1 per-stage smem bytes (A 16K + B 16K)

// gi scratch in fp16: [pair][t][b][g]  (1.61 GB)
__device__ __half g_gi[(size_t)NPAIR * SEQ * BATCH * G3];
__device__ __half g_xh[(size_t)BATCH * SEQ * DIM];
__device__ __half g_wh[(size_t)NPAIR * G3 * DIM];

__device__ __forceinline__ __half* gi_ptr(int p) {
    return g_gi + (size_t)p * ((size_t)SEQ * BATCH * G3);
}

__device__ __forceinline__ void mma_f16(float* c, const uint32_t* a, const uint32_t* b) {
    asm volatile(
        "mma.sync.aligned.m16n8k16.row.col.f32.f16.f16.f32 "
        "{%0,%1,%2,%3}, {%4,%5,%6,%7}, {%8,%9}, {%0,%1,%2,%3};\n"
        : "+f"(c[0]), "+f"(c[1]), "+f"(c[2]), "+f"(c[3])
        : "r"(a[0]), "r"(a[1]), "r"(a[2]), "r"(a[3]), "r"(b[0]), "r"(b[1]));
}
__device__ __forceinline__ void ldm_x4(uint32_t& r0, uint32_t& r1, uint32_t& r2, uint32_t& r3,
                                       uint32_t addr) {
    asm volatile("ldmatrix.sync.aligned.m8n8.x4.shared.b16 {%0,%1,%2,%3}, [%4];"
                 : "=r"(r0), "=r"(r1), "=r"(r2), "=r"(r3) : "r"(addr));
}
__device__ __forceinline__ uint32_t f2h2(float a, float b) {
    __half2 h = __floats2half2_rn(a, b);
    return *(uint32_t*)&h;
}
__device__ __forceinline__ float tanh_mufu(float x) {
    float y;
    asm("tanh.approx.f32 %0, %1;" : "=f"(y) : "f"(x));
    return y;
}
__device__ __forceinline__ float sigmoid_fast(float x) {
    return fmaf(tanh_mufu(0.5f * x), 0.5f, 0.5f);
}

// ===========================================================================
// Phase 0: convert x and Wih to fp16 once.
// ===========================================================================
__global__ __launch_bounds__(256) void convert_kernel(
    const float* __restrict__ x, const float* __restrict__ Wih)
{
    const size_t nx = (size_t)BATCH * SEQ * DIM / 4;
    const size_t nw = (size_t)NPAIR * G3 * DIM / 4;
    size_t i = (size_t)blockIdx.x * blockDim.x + threadIdx.x;
    if (i < nx) {
        float4 v = ((const float4*)x)[i];
        __half2* d = (__half2*)g_xh;
        d[2 * i]     = __floats2half2_rn(v.x, v.y);
        d[2 * i + 1] = __floats2half2_rn(v.z, v.w);
    } else if (i < nx + nw) {
        size_t j = i - nx;
        float4 v = ((const float4*)Wih)[j];
        __half2* d = (__half2*)g_wh;
        d[2 * j]     = __floats2half2_rn(v.x, v.y);
        d[2 * j + 1] = __floats2half2_rn(v.z, v.w);
    }
}

// ===========================================================================
// Phase 1: gi[p][t][b][g] = x[b,t,:].Wih[p][g,:] + bih[g] + (g<256 ? bhh[g]:0)
// fp16 smem + ldmatrix + m16n8k16, f32 accum. BM=128, BN=128, BK=64.
// 3-stage cp.async pipeline, ONE __syncthreads per k-chunk.
// ===========================================================================
__global__ __launch_bounds__(256, 2) void gi_gemm_kernel(
    const float* __restrict__ bih, const float* __restrict__ bhh)
{
    extern __shared__ __half smh[];

    const int tid  = threadIdx.x;
    const int wid  = tid >> 5, lane = tid & 31;
    const int gid  = lane >> 2, tig = lane & 3;
    const int wm   = wid >> 2;
    const int wn   = wid & 3;
    const int mblk = blockIdx.x;      // 0..511
    const int nblk = blockIdx.y;      // 0..2
    const int p    = blockIdx.z;      // 0..31
    const int g0   = nblk * 128;

    const __half* Wp = g_wh + (size_t)p * G3 * DIM;
    const uint32_t sm_u = (uint32_t)__cvta_generic_to_shared(smh);

    const __half* gA[4]; const __half* gB[4];
    uint32_t offAB[4];
#pragma unroll
    for (int i = 0; i < 4; i++) {
        int flat = tid + 256 * i;
        int row = flat >> 3, c = flat & 7;
        int m = mblk * 128 + row;
        int b = m & 31, t = m >> 5;
        gA[i] = g_xh + ((size_t)b * SEQ + t) * DIM + c * 8;
        gB[i] = Wp + (size_t)(g0 + row) * DIM + c * 8;
        offAB[i] = (uint32_t)(row * 128 + ((c ^ (row & 7)) * 16));
    }

    auto issueAB = [&](int kc, int st) {
        const int ko = kc * 64;
        const uint32_t sa = sm_u + (uint32_t)st * ST1;
        const uint32_t sb = sa + 16384u;
#pragma unroll
        for (int i = 0; i < 4; i++) {
            asm volatile("cp.async.cg.shared.global [%0], [%1], 16;\n"
                         :: "r"(sa + offAB[i]), "l"(gA[i] + ko) : "memory");
            asm volatile("cp.async.cg.shared.global [%0], [%1], 16;\n"
                         :: "r"(sb + offAB[i]), "l"(gB[i] + ko) : "memory");
        }
        asm volatile("cp.async.commit_group;\n" ::: "memory");
    };

    float acc[4][4][4];
#pragma unroll
    for (int mt = 0; mt < 4; mt++)
#pragma unroll
        for (int nt = 0; nt < 4; nt++)
#pragma unroll
            for (int q = 0; q < 4; q++) acc[mt][nt][q] = 0.0f;

    issueAB(0, 0);
    issueAB(1, 1);

    const int lrow = lane & 15;
    const int lhi  = lane >> 4;
    int rowA[4];
#pragma unroll
    for (int mt = 0; mt < 4; mt++) rowA[mt] = wm * 64 + mt * 16 + lrow;
    int rowB[2];
#pragma unroll
    for (int q = 0; q < 2; q++)
        rowB[q] = wn * 32 + q * 16 + ((lane >> 4) << 3) + (lane & 7);
    const int cB = (lane >> 3) & 1;

#pragma unroll
    for (int kc = 0; kc < 4; kc++) {
        if (kc < 3) { asm volatile("cp.async.wait_group 1;\n" ::: "memory"); }
        else        { asm volatile("cp.async.wait_group 0;\n" ::: "memory"); }
        __syncthreads();
        if (kc + 2 < 4) issueAB(kc + 2, (kc + 2) % 3);

        const int st = kc % 3;
        const uint32_t Ab = sm_u + (uint32_t)st * ST1;
        const uint32_t Bb = Ab + 16384u;
#pragma unroll
        for (int ks = 0; ks < 4; ks++) {
            uint32_t af[4][4], bf[4][2];
#pragma unroll
            for (int mt = 0; mt < 4; mt++) {
                uint32_t addr = Ab + (uint32_t)(rowA[mt] * 128 +
                                (((ks * 2 + lhi) ^ (rowA[mt] & 7)) * 16));
                ldm_x4(af[mt][0], af[mt][1], af[mt][2], af[mt][3], addr);
            }
#pragma unroll
            for (int q = 0; q < 2; q++) {
                uint32_t addr = Bb + (uint32_t)(rowB[q] * 128 +
                                (((ks * 2 + cB) ^ (rowB[q] & 7)) * 16));
                ldm_x4(bf[2 * q][0], bf[2 * q][1], bf[2 * q + 1][0], bf[2 * q + 1][1], addr);
            }
#pragma unroll
            for (int mt = 0; mt < 4; mt++)
#pragma unroll
                for (int nt = 0; nt < 4; nt++)
                    mma_f16(acc[mt][nt], af[mt], bf[nt]);
        }
    }

    // epilogue: add folded bias, store fp16
    const float* bih_p = bih + (size_t)p * G3;
    const float* bhh_p = bhh + (size_t)p * G3;
    __half* gi = gi_ptr(p);
#pragma unroll
    for (int nt = 0; nt < 4; nt++) {
        int gc0 = g0 + wn * 32 + nt * 8 + 2 * tig;
        float bias0 = bih_p[gc0]     + ((gc0     < 256) ? bhh_p[gc0]     : 0.0f);
        float bias1 = bih_p[gc0 + 1] + ((gc0 + 1 < 256) ? bhh_p[gc0 + 1] : 0.0f);
#pragma unroll
        for (int mt = 0; mt < 4; mt++) {
            int m0 = mblk * 128 + wm * 64 + mt * 16 + gid;
            __half2 v0 = __floats2half2_rn(acc[mt][nt][0] + bias0, acc[mt][nt][1] + bias1);
            __half2 v1 = __floats2half2_rn(acc[mt][nt][2] + bias0, acc[mt][nt][3] + bias1);
            *(__half2*)(gi + (size_t)m0 * G3 + gc0)       = v0;
            *(__half2*)(gi + (size_t)(m0 + 8) * G3 + gc0) = v1;
        }
    }
}

// ===========================================================================
// Phase 2: recurrent sweep, register-resident gates, ONE barrier per step.
// Latency fix: each gate's 8-deep dependent HMMA chain split into TWO
// independent depth-4 chains (6 chains/warp, interleaved issue), combined in
// f32 at the end. Serial MMA spine ~480 -> ~240 cyc; issue floor unchanged.
// ===========================================================================
__global__ __launch_bounds__(256, 1) void gru_rec_kernel(
    const float* __restrict__ Whh, const float* __restrict__ bhh,
    const int* __restrict__ amask, float* __restrict__ out)
{
    extern __shared__ char dyn[];
    __half (*h_sm)[BC][136] = (__half(*)[BC][136])dyn;
    uint32_t (*mask_sm)[64] = (uint32_t(*)[64])(dyn + 4352);
    int* len_sm             = (int*)(dyn + 6400);          // 8 ints
    __half* gi_ring         = (__half*)(dyn + 6464);

    const int tid = threadIdx.x;
    const int wid = tid >> 5, lane = tid & 31;
    const int gid = lane >> 2, tig = lane & 3;
    const int chunk = blockIdx.x;     // 0..3
    const int p     = blockIdx.y;     // 0..31
    const int l = p >> 1, dir = p & 1;
    const int b0 = chunk * BC;
    const float* Whh_p = Whh + (size_t)p * G3 * HID;
    const float* bhh_p = bhh + (size_t)p * G3;

    // A fragments: gate i (r/z/n), rows i*128 + 16*wid .. +15
    uint32_t A[3][8][4];
#pragma unroll
    for (int i = 0; i < 3; i++) {
        int r0 = i * 128 + 16 * wid + gid;
        int r1 = r0 + 8;
#pragma unroll
        for (int kk = 0; kk < 8; kk++) {
            int k0 = kk * 16 + tig * 2;
            int k1 = k0 + 8;
            float2 v00 = *(const float2*)(Whh_p + (size_t)r0 * HID + k0);
            float2 v10 = *(const float2*)(Whh_p + (size_t)r1 * HID + k0);
            float2 v01 = *(const float2*)(Whh_p + (size_t)r0 * HID + k1);
            float2 v11 = *(const float2*)(Whh_p + (size_t)r1 * HID + k1);
            A[i][kk][0] = f2h2(v00.x, v00.y);
            A[i][kk][1] = f2h2(v10.x, v10.y);
            A[i][kk][2] = f2h2(v01.x, v01.y);
            A[i][kk][3] = f2h2(v11.x, v11.y);
        }
    }
    const int j0 = 16 * wid + gid;
    const float bias_n0 = bhh_p[256 + j0];
    const float bias_n1 = bhh_p[256 + j0 + 8];

    {   // pack mask bits + per-row length (mask is a prefix of ones)
        const int* mb = amask + (size_t)(b0 + wid) * SEQ;
        int cnt = 0;
        for (int w = 0; w < 64; w++) {
            unsigned bit = (mb[w * 32 + lane] != 0) ? 1u : 0u;
            unsigned word = __ballot_sync(0xffffffffu, bit);
            if (lane == 0) mask_sm[wid][w] = word;
            cnt += __popc(word);
        }
        if (lane == 0) len_sm[wid] = cnt;
    }
    for (int i = tid; i < 2 * BC * 136; i += 256) (&h_sm[0][0][0])[i] = __float2half(0.0f);
    __syncthreads();

    int maxlen = len_sm[0];
#pragma unroll
    for (int b = 1; b < BC; b++) maxlen = max(maxlen, len_sm[b]);

    const __half* gi = gi_ptr(p);
    const uint32_t gi_smu = (uint32_t)__cvta_generic_to_shared(gi_ring);

    auto issue = [&](int t, int stage) {
#pragma unroll
        for (int i = 0; i < 2; i++) {
            int o = tid + 256 * i;
            if (o < 384) {
                int row = o / 48, q = o % 48;
                const __half* src = gi + ((size_t)t * 32 + b0 + row) * G3 + q * 8;
                uint32_t dst = gi_smu + (uint32_t)((stage * BC + row) * GIP + q * 8) * 2u;
                asm volatile("cp.async.cg.shared.global [%0], [%1], 16;\n"
                             :: "r"(dst), "l"(src) : "memory");
            }
        }
    };

    // prologue: stages 0..6
    for (int k = 0; k < NSTAGE - 1; k++) {
        issue(dir ? (maxlen - 1 - k) : k, k);
        asm volatile("cp.async.commit_group;\n" ::: "memory");
    }
    asm volatile("cp.async.wait_group 6;\n" ::: "memory");
    __syncthreads();

    const int bq0 = 2 * tig, bq1 = 2 * tig + 1;
    float h[4] = {0.f, 0.f, 0.f, 0.f};

    for (int s = 0; s < maxlen; s++) {
        const int t = dir ? (maxlen - 1 - s) : s;
        const int stage = s & (NSTAGE - 1);
        const int cur = s & 1, nxt = cur ^ 1;

        if (s + NSTAGE - 1 < maxlen)
            issue(dir ? (maxlen - 1 - (s + NSTAGE - 1)) : (s + NSTAGE - 1),
                  (s + NSTAGE - 1) & (NSTAGE - 1));
        asm volatile("cp.async.commit_group;\n" ::: "memory");

        // MMA from h_sm[cur]: SIX independent depth-4 chains, interleaved
        float crA[4] = {0.f, 0.f, 0.f, 0.f}, crB[4] = {0.f, 0.f, 0.f, 0.f};
        float czA[4] = {0.f, 0.f, 0.f, 0.f}, czB[4] = {0.f, 0.f, 0.f, 0.f};
        float cnA[4], cnB[4] = {0.f, 0.f, 0.f, 0.f};
        cnA[0] = bias_n0; cnA[1] = bias_n0; cnA[2] = bias_n1; cnA[3] = bias_n1;
#pragma unroll
        for (int kk = 0; kk < 4; kk++) {
            uint32_t bfa[2], bfb[2];
            bfa[0] = *(const uint32_t*)&h_sm[cur][gid][kk * 16 + tig * 2];
            bfa[1] = *(const uint32_t*)&h_sm[cur][gid][kk * 16 + tig * 2 + 8];
            bfb[0] = *(const uint32_t*)&h_sm[cur][gid][(kk + 4) * 16 + tig * 2];
            bfb[1] = *(const uint32_t*)&h_sm[cur][gid][(kk + 4) * 16 + tig * 2 + 8];
            mma_f16(crA, A[0][kk], bfa);
            mma_f16(czA, A[1][kk], bfa);
            mma_f16(cnA, A[2][kk], bfa);
            mma_f16(crB, A[0][kk + 4], bfb);
            mma_f16(czB, A[1][kk + 4], bfb);
            mma_f16(cnB, A[2][kk + 4], bfb);
        }
        float cr[4], cz[4], cn[4];
#pragma unroll
        for (int q = 0; q < 4; q++) {
            cr[q] = crA[q] + crB[q];
            cz[q] = czA[q] + czB[q];
            cn[q] = cnA[q] + cnB[q];
        }

        const unsigned mw0 = mask_sm[bq0][t >> 5];
        const unsigned mw1 = mask_sm[bq1][t >> 5];
        const bool v0 = (mw0 >> (t & 31)) & 1u;
        const bool v1 = (mw1 >> (t & 31)) & 1u;
        const __half* gp0 = gi_ring + (size_t)(stage * BC + bq0) * GIP;
        const __half* gp1 = gp0 + GIP;
#pragma unroll
        for (int m = 0; m < 2; m++) {
            const int j = j0 + 8 * m;
#pragma unroll
            for (int bs = 0; bs < 2; bs++) {
                const int q = 2 * m + bs;
                const __half* gp = bs ? gp1 : gp0;
                float gir = __half2float(gp[j]);
                float giz = __half2float(gp[128 + j]);
                float gin = __half2float(gp[256 + j]);
                float r = sigmoid_fast(gir + cr[q]);
                float z = sigmoid_fast(giz + cz[q]);
                float n = tanh_mufu(gin + r * cn[q]);
                float hn = n + z * (h[q] - n);
                bool valid = bs ? v1 : v0;
                if (valid) h[q] = hn;
                h_sm[nxt][bs ? bq1 : bq0][j] = __float2half(h[q]);
            }
        }
        asm volatile("cp.async.wait_group 6;\n" ::: "memory");
        __syncthreads();
    }

#pragma unroll
    for (int m = 0; m < 2; m++) {
        const int j = j0 + 8 * m;
        const int col = (dir == 1) ? j : (128 + j);
#pragma unroll
        for (int bs = 0; bs < 2; bs++) {
            const int q = 2 * m + bs;
            const int bg = b0 + (bs ? bq1 : bq0);
            out[((size_t)bg * NLAB + l) * 256 + col] = h[q];
        }
    }
}

extern "C" void kernel_launch(void* const* d_in, const int* in_sizes, int n_in,
                              void* d_out, int out_size) {
    const float* x     = (const float*)d_in[0];
    const int*   amask = (const int*)d_in[1];
    // d_in[2] = label: always arange(L) by construction.
    const float* Wih   = (const float*)d_in[3];
    const float* Whh   = (const float*)d_in[4];
    const float* bih   = (const float*)d_in[5];
    const float* bhh   = (const float*)d_in[6];
    float*       out   = (float*)d_out;

    cudaFuncSetAttribute(gi_gemm_kernel, cudaFuncAttributeMaxDynamicSharedMemorySize, 98304);
    cudaFuncSetAttribute(gru_rec_kernel, cudaFuncAttributeMaxDynamicSharedMemorySize, 57344);

    const size_t nchunks = (size_t)BATCH * SEQ * DIM / 4 + (size_t)NPAIR * G3 * DIM / 4;
    convert_kernel<<<(unsigned)((nchunks + 255) / 256), 256>>>(x, Wih);

    dim3 g1(512, 3, 32);
    gi_gemm_kernel<<<g1, 256, 98304>>>(bih, bhh);

    dim3 g2(4, 32);
    gru_rec_kernel<<<g2, 256, 57344>>>(Whh, bhh, amask, out);
}

// round 14
// speedup vs baseline: 1.0807x; 1.0807x over previous
#include <cuda_runtime.h>
#include <cuda_fp16.h>
#include <cstdint>

#define NLAB 16
#define DIM  256
#define HID  128
#define BATCH 32
#define SEQ  2048
#define G3   384
#define NPAIR 32
#define BC   8
#define GIP  392
#define TS   8              // timesteps per produced segment (M = TS*BC = 64)

// smem byte offsets (fused kernel)
#define OFF_H    0          // h_sm[2][8][136] half            = 4352
#define OFF_MASK 4352       // mask[8][64] u32                 = 2048
#define OFF_LEN  6400       // len[8] int                      = 32
#define OFF_MB   6432       // mbar: full0,full1,empty0,empty1 = 32
#define OFF_GI   6464       // gi ring [2][64][392] half       = 100352
#define OFF_A    106816     // A tile [4 kc][64][64] half      = 32768
#define OFF_B    139584     // B ring [2][384][32] half        = 49152
#define SMEM_TOTAL 188736

__device__ __half g_xh[(size_t)BATCH * SEQ * DIM];
__device__ __half g_wh[(size_t)NPAIR * G3 * DIM];

__device__ __forceinline__ void mma_f16(float* c, const uint32_t* a, const uint32_t* b) {
    asm volatile(
        "mma.sync.aligned.m16n8k16.row.col.f32.f16.f16.f32 "
        "{%0,%1,%2,%3}, {%4,%5,%6,%7}, {%8,%9}, {%0,%1,%2,%3};\n"
        : "+f"(c[0]), "+f"(c[1]), "+f"(c[2]), "+f"(c[3])
        : "r"(a[0]), "r"(a[1]), "r"(a[2]), "r"(a[3]), "r"(b[0]), "r"(b[1]));
}
__device__ __forceinline__ void mma_f16h(uint32_t* c, const uint32_t* a, const uint32_t* b) {
    asm volatile(
        "mma.sync.aligned.m16n8k16.row.col.f16.f16.f16.f16 "
        "{%0,%1}, {%2,%3,%4,%5}, {%6,%7}, {%0,%1};\n"
        : "+r"(c[0]), "+r"(c[1])
        : "r"(a[0]), "r"(a[1]), "r"(a[2]), "r"(a[3]), "r"(b[0]), "r"(b[1]));
}
__device__ __forceinline__ void ldm_x4(uint32_t& r0, uint32_t& r1, uint32_t& r2, uint32_t& r3,
                                       uint32_t addr) {
    asm volatile("ldmatrix.sync.aligned.m8n8.x4.shared.b16 {%0,%1,%2,%3}, [%4];"
                 : "=r"(r0), "=r"(r1), "=r"(r2), "=r"(r3) : "r"(addr));
}
__device__ __forceinline__ uint32_t f2h2(float a, float b) {
    __half2 h = __floats2half2_rn(a, b);
    return *(uint32_t*)&h;
}
__device__ __forceinline__ float tanh_mufu(float x) {
    float y;
    asm("tanh.approx.f32 %0, %1;" : "=f"(y) : "f"(x));
    return y;
}
__device__ __forceinline__ float sigmoid_fast(float x) {
    return fmaf(tanh_mufu(0.5f * x), 0.5f, 0.5f);
}
__device__ __forceinline__ void mbar_init(uint32_t mbar, uint32_t cnt) {
    asm volatile("mbarrier.init.shared.b64 [%0], %1;" :: "r"(mbar), "r"(cnt) : "memory");
}
__device__ __forceinline__ void mbar_arrive(uint32_t mbar) {
    asm volatile("mbarrier.arrive.release.cta.shared::cta.b64 _, [%0];"
                 :: "r"(mbar) : "memory");
}
// acquire variant: generic ld.shared after this wait is ordered (ptx_helpers rule)
__device__ __forceinline__ void mbar_wait(uint32_t mbar, uint32_t parity) {
    asm volatile(
        "{\n\t.reg .pred P1;\n\t"
        "WAIT_%=:\n\t"
        "mbarrier.try_wait.parity.acquire.cta.shared::cta.b64 P1, [%0], %1, 0x989680;\n\t"
        "@P1 bra.uni DONE_%=;\n\t"
        "bra.uni WAIT_%=;\n\t"
        "DONE_%=:\n\t}"
        :: "r"(mbar), "r"(parity) : "memory");
}

// ===========================================================================
// Phase 0: convert x and Wih to fp16 once.
// ===========================================================================
__global__ __launch_bounds__(256) void convert_kernel(
    const float* __restrict__ x, const float* __restrict__ Wih)
{
    const size_t nx = (size_t)BATCH * SEQ * DIM / 4;
    const size_t nw = (size_t)NPAIR * G3 * DIM / 4;
    size_t i = (size_t)blockIdx.x * blockDim.x + threadIdx.x;
    if (i < nx) {
        float4 v = ((const float4*)x)[i];
        __half2* d = (__half2*)g_xh;
        d[2 * i]     = __floats2half2_rn(v.x, v.y);
        d[2 * i + 1] = __floats2half2_rn(v.z, v.w);
    } else if (i < nx + nw) {
        size_t j = i - nx;
        float4 v = ((const float4*)Wih)[j];
        __half2* d = (__half2*)g_wh;
        d[2 * j]     = __floats2half2_rn(v.x, v.y);
        d[2 * j + 1] = __floats2half2_rn(v.z, v.w);
    }
}

// ===========================================================================
// Fused kernel. Block = (chunk, pair), 384 threads.
//  warps 0-7 : recurrence (gi from smem ring; biases in gate math)
//  warps 8-11: producer — gi GEMM per 8-step segment into 2-buffer smem ring.
// Sync: mbarriers full[2] (128 arrivals) / empty[2] (256 arrivals);
//       rec-internal bar.sync 1,256; producer-internal bar.sync 2,128.
// ===========================================================================
__global__ __launch_bounds__(384, 1) void gru_fused_kernel(
    const float* __restrict__ Whh, const float* __restrict__ bih,
    const float* __restrict__ bhh, const int* __restrict__ amask,
    float* __restrict__ out)
{
    extern __shared__ char dyn[];
    __half (*h_sm)[BC][136] = (__half(*)[BC][136])(dyn + OFF_H);
    uint32_t (*mask_sm)[64] = (uint32_t(*)[64])(dyn + OFF_MASK);
    int* len_sm             = (int*)(dyn + OFF_LEN);
    __half* gi_sm           = (__half*)(dyn + OFF_GI);
    const uint32_t smem_u   = (uint32_t)__cvta_generic_to_shared(dyn);
    const uint32_t mb_full0 = smem_u + OFF_MB;
    const uint32_t mb_empty0 = smem_u + OFF_MB + 16;

    const int tid = threadIdx.x;
    const int wid = tid >> 5, lane = tid & 31;
    const int gid = lane >> 2, tig = lane & 3;
    const int chunk = blockIdx.x;     // 0..3
    const int p     = blockIdx.y;     // 0..31
    const int l = p >> 1, dir = p & 1;
    const int b0 = chunk * BC;

    // ---- shared setup (all 384 threads) ----
    if (tid == 0) {
        mbar_init(mb_full0, 128);
        mbar_init(mb_full0 + 8, 128);
        mbar_init(mb_empty0, 256);
        mbar_init(mb_empty0 + 8, 256);
    }
    if (wid < 8) {  // mask pack + lengths (rec warps, one batch row each)
        const int* mb = amask + (size_t)(b0 + wid) * SEQ;
        int cnt = 0;
        for (int w = 0; w < 64; w++) {
            unsigned bit = (mb[w * 32 + lane] != 0) ? 1u : 0u;
            unsigned word = __ballot_sync(0xffffffffu, bit);
            if (lane == 0) mask_sm[wid][w] = word;
            cnt += __popc(word);
        }
        if (lane == 0) len_sm[wid] = cnt;
    }
    for (int i = tid; i < 2 * BC * 136; i += 384) (&h_sm[0][0][0])[i] = __float2half(0.0f);
    __syncthreads();

    int maxlen = len_sm[0];
#pragma unroll
    for (int b = 1; b < BC; b++) maxlen = max(maxlen, len_sm[b]);
    const int nseg = (maxlen + TS - 1) / TS;

    if (wid < 8) {
        // =================== CONSUMER: recurrence ===================
        const float* Whh_p = Whh + (size_t)p * G3 * HID;
        const float* bih_p = bih + (size_t)p * G3;
        const float* bhh_p = bhh + (size_t)p * G3;

        uint32_t A[3][8][4];
#pragma unroll
        for (int i = 0; i < 3; i++) {
            int r0 = i * 128 + 16 * wid + gid;
            int r1 = r0 + 8;
#pragma unroll
            for (int kk = 0; kk < 8; kk++) {
                int k0 = kk * 16 + tig * 2;
                int k1 = k0 + 8;
                float2 v00 = *(const float2*)(Whh_p + (size_t)r0 * HID + k0);
                float2 v10 = *(const float2*)(Whh_p + (size_t)r1 * HID + k0);
                float2 v01 = *(const float2*)(Whh_p + (size_t)r0 * HID + k1);
                float2 v11 = *(const float2*)(Whh_p + (size_t)r1 * HID + k1);
                A[i][kk][0] = f2h2(v00.x, v00.y);
                A[i][kk][1] = f2h2(v10.x, v10.y);
                A[i][kk][2] = f2h2(v01.x, v01.y);
                A[i][kk][3] = f2h2(v11.x, v11.y);
            }
        }
        const int j0 = 16 * wid + gid;
        // biases (gi is raw GEMM output): r/z get bih+bhh; n gets bih additive
        // and bhh_n inside the accumulator (multiplied by r).
        float br[2], bz[2], bin[2], bnh[2];
#pragma unroll
        for (int m = 0; m < 2; m++) {
            int j = j0 + 8 * m;
            br[m]  = bih_p[j]       + bhh_p[j];
            bz[m]  = bih_p[128 + j] + bhh_p[128 + j];
            bin[m] = bih_p[256 + j];
            bnh[m] = bhh_p[256 + j];
        }

        const int bq0 = 2 * tig, bq1 = 2 * tig + 1;
        float h[4] = {0.f, 0.f, 0.f, 0.f};

        for (int s = 0; s < maxlen; s++) {
            const int t = dir ? (maxlen - 1 - s) : s;
            const int tt = s & (TS - 1);
            const int buf = (s >> 3) & 1;
            const int cur = s & 1, nxt = cur ^ 1;

            if (tt == 0) mbar_wait(mb_full0 + 8 * buf, (s >> 4) & 1);

            float cr[4] = {0.f, 0.f, 0.f, 0.f};
            float cz[4] = {0.f, 0.f, 0.f, 0.f};
            float cn[4];
            cn[0] = bnh[0]; cn[1] = bnh[0]; cn[2] = bnh[1]; cn[3] = bnh[1];
#pragma unroll
            for (int kk = 0; kk < 8; kk++) {
                uint32_t bfr[2];
                bfr[0] = *(const uint32_t*)&h_sm[cur][gid][kk * 16 + tig * 2];
                bfr[1] = *(const uint32_t*)&h_sm[cur][gid][kk * 16 + tig * 2 + 8];
                mma_f16(cr, A[0][kk], bfr);
                mma_f16(cz, A[1][kk], bfr);
                mma_f16(cn, A[2][kk], bfr);
            }

            const unsigned mw0 = mask_sm[bq0][t >> 5];
            const unsigned mw1 = mask_sm[bq1][t >> 5];
            const bool v0 = (mw0 >> (t & 31)) & 1u;
            const bool v1 = (mw1 >> (t & 31)) & 1u;
            const __half* gp0 = gi_sm + (size_t)(buf * 64 + tt * 8 + bq0) * GIP;
            const __half* gp1 = gp0 + GIP;
#pragma unroll
            for (int m = 0; m < 2; m++) {
                const int j = j0 + 8 * m;
#pragma unroll
                for (int bs = 0; bs < 2; bs++) {
                    const int q = 2 * m + bs;
                    const __half* gp = bs ? gp1 : gp0;
                    float gir = __half2float(gp[j]);
                    float giz = __half2float(gp[128 + j]);
                    float gin = __half2float(gp[256 + j]);
                    float r = sigmoid_fast(gir + cr[q] + br[m]);
                    float z = sigmoid_fast(giz + cz[q] + bz[m]);
                    float n = tanh_mufu(gin + bin[m] + r * cn[q]);
                    float hn = n + z * (h[q] - n);
                    bool valid = bs ? v1 : v0;
                    if (valid) h[q] = hn;
                    h_sm[nxt][bs ? bq1 : bq0][j] = __float2half(h[q]);
                }
            }
            asm volatile("bar.sync 1, 256;" ::: "memory");   // rec warps only
            if (tt == TS - 1 || s == maxlen - 1)
                mbar_arrive(mb_empty0 + 8 * buf);
        }

#pragma unroll
        for (int m = 0; m < 2; m++) {
            const int j = j0 + 8 * m;
            const int col = (dir == 1) ? j : (128 + j);
#pragma unroll
            for (int bs = 0; bs < 2; bs++) {
                const int q = 2 * m + bs;
                const int bg = b0 + (bs ? bq1 : bq0);
                out[((size_t)bg * NLAB + l) * 256 + col] = h[q];
            }
        }
    } else {
        // =================== PRODUCER: gi GEMM ===================
        const int pw = wid - 8;            // 0..3
        const int ptid = tid - 256;        // 0..127
        const __half* Wp = g_wh + (size_t)p * G3 * DIM;
        const uint32_t Asm = smem_u + OFF_A;
        const uint32_t Bsm = smem_u + OFF_B;
        const int lrow = lane & 15;
        const int lhi  = lane >> 4;
        const int rB_lo = ((lane >> 4) << 3) + (lane & 7);
        const int cB = (lane >> 3) & 1;

        for (int j = 0; j < nseg; j++) {
            const int buf = j & 1;
            if (j >= 2) mbar_wait(mb_empty0 + 8 * buf, ((j - 2) >> 1) & 1);
            asm volatile("bar.sync 2, 128;" ::: "memory");   // old A fully consumed

            // issue A tile (M=64 rows = tt*8+b, K=256)
            const int tbase = dir ? (maxlen - 1 - TS * j) : TS * j;
#pragma unroll
            for (int i = 0; i < 16; i++) {
                int flat = ptid + 128 * i;             // 0..2047
                int kc = flat >> 9, rem = flat & 511;
                int row = rem >> 3, c = rem & 7;
                int b = row & 7, tt = row >> 3;
                int t = dir ? (tbase - tt) : (tbase + tt);
                t = min(max(t, 0), SEQ - 1);
                const __half* src = g_xh + ((size_t)(b0 + b) * SEQ + t) * DIM + kc * 64 + c * 8;
                uint32_t dst = Asm + (uint32_t)(kc * 8192 + row * 128 + ((c ^ (row & 7)) * 16));
                asm volatile("cp.async.cg.shared.global [%0], [%1], 16;\n"
                             :: "r"(dst), "l"(src) : "memory");
            }
            asm volatile("cp.async.commit_group;\n" ::: "memory");
            // issue B chunks 0,1 (each: 384 rows x 32 k)
#pragma unroll
            for (int kc32 = 0; kc32 < 2; kc32++) {
#pragma unroll
                for (int i = 0; i < 12; i++) {
                    int flat = ptid + 128 * i;         // 0..1535
                    int row = flat >> 2, c = flat & 3;
                    const __half* src = Wp + (size_t)row * DIM + kc32 * 32 + c * 8;
                    uint32_t dst = Bsm + (uint32_t)(kc32 * 24576 + row * 64 + ((c ^ (row & 3)) * 16));
                    asm volatile("cp.async.cg.shared.global [%0], [%1], 16;\n"
                                 :: "r"(dst), "l"(src) : "memory");
                }
                asm volatile("cp.async.commit_group;\n" ::: "memory");
            }

            // accumulators: rz in f16 (8 ntiles), n in f32 (4 ntiles), 4 mtiles
            uint32_t accH[4][8][2];
            float accF[4][4][4];
#pragma unroll
            for (int mt = 0; mt < 4; mt++) {
#pragma unroll
                for (int e = 0; e < 8; e++) { accH[mt][e][0] = 0u; accH[mt][e][1] = 0u; }
#pragma unroll
                for (int f = 0; f < 4; f++)
#pragma unroll
                    for (int q = 0; q < 4; q++) accF[mt][f][q] = 0.0f;
            }

            for (int kc32 = 0; kc32 < 8; kc32++) {
                asm volatile("cp.async.wait_group 1;\n" ::: "memory");
                asm volatile("bar.sync 2, 128;" ::: "memory");   // chunk kc32 visible
                const uint32_t Bb = Bsm + (uint32_t)((kc32 & 1) * 24576);
#pragma unroll
                for (int ksb = 0; ksb < 2; ksb++) {
                    const int ks = kc32 * 2 + ksb;
                    const uint32_t Abk = Asm + (uint32_t)((ks >> 2) * 8192);
                    const int ach = ((ks & 3) * 2 + lhi);
                    // B fragments: 4 rz pairs + 2 n pairs
                    uint32_t bfrz[4][4], bfn[2][4];
#pragma unroll
                    for (int pr = 0; pr < 4; pr++) {
                        int nb = (pr < 2 ? 0 : 128) + 32 * pw + (pr & 1) * 16;
                        uint32_t addr = Bb + (uint32_t)((nb + rB_lo) * 64 +
                                        (((ksb * 2 + cB) ^ ((nb + rB_lo) & 3)) * 16));
                        ldm_x4(bfrz[pr][0], bfrz[pr][1], bfrz[pr][2], bfrz[pr][3], addr);
                    }
#pragma unroll
                    for (int pr = 0; pr < 2; pr++) {
                        int nb = 256 + 32 * pw + pr * 16;
                        uint32_t addr = Bb + (uint32_t)((nb + rB_lo) * 64 +
                                        (((ksb * 2 + cB) ^ ((nb + rB_lo) & 3)) * 16));
                        ldm_x4(bfn[pr][0], bfn[pr][1], bfn[pr][2], bfn[pr][3], addr);
                    }
                    // single A-fragment load per m-tile, all 12 MMAs use it
#pragma unroll
                    for (int mt = 0; mt < 4; mt++) {
                        int rA = mt * 16 + lrow;
                        uint32_t af[4];
                        uint32_t addr = Abk + (uint32_t)(rA * 128 + ((ach ^ (rA & 7)) * 16));
                        ldm_x4(af[0], af[1], af[2], af[3], addr);
#pragma unroll
                        for (int pr = 0; pr < 4; pr++) {
                            mma_f16h(accH[mt][2 * pr],     af, &bfrz[pr][0]);
                            mma_f16h(accH[mt][2 * pr + 1], af, &bfrz[pr][2]);
                        }
                        mma_f16(accF[mt][0], af, &bfn[0][0]);
                        mma_f16(accF[mt][1], af, &bfn[0][2]);
                        mma_f16(accF[mt][2], af, &bfn[1][0]);
                        mma_f16(accF[mt][3], af, &bfn[1][2]);
                    }
                }
                asm volatile("bar.sync 2, 128;" ::: "memory");   // chunk reads done
                if (kc32 + 2 < 8) {
                    const int nk = kc32 + 2;
#pragma unroll
                    for (int i = 0; i < 12; i++) {
                        int flat = ptid + 128 * i;
                        int row = flat >> 2, c = flat & 3;
                        const __half* src = Wp + (size_t)row * DIM + nk * 32 + c * 8;
                        uint32_t dst = Bsm + (uint32_t)((nk & 1) * 24576 + row * 64 +
                                                        ((c ^ (row & 3)) * 16));
                        asm volatile("cp.async.cg.shared.global [%0], [%1], 16;\n"
                                     :: "r"(dst), "l"(src) : "memory");
                    }
                }
                asm volatile("cp.async.commit_group;\n" ::: "memory");
            }

            // epilogue: store raw gi (biases applied in recurrence)
            __half* gib = gi_sm + (size_t)buf * 64 * GIP;
#pragma unroll
            for (int mt = 0; mt < 4; mt++) {
                int rr0 = mt * 16 + gid, rr1 = rr0 + 8;
#pragma unroll
                for (int e = 0; e < 8; e++) {
                    int col = ((e < 4) ? (32 * pw + 8 * e) : (128 + 32 * pw + 8 * (e - 4)))
                              + 2 * tig;
                    *(uint32_t*)(gib + (size_t)rr0 * GIP + col) = accH[mt][e][0];
                    *(uint32_t*)(gib + (size_t)rr1 * GIP + col) = accH[mt][e][1];
                }
#pragma unroll
                for (int f = 0; f < 4; f++) {
                    int col = 256 + 32 * pw + 8 * f + 2 * tig;
                    *(uint32_t*)(gib + (size_t)rr0 * GIP + col) =
                        f2h2(accF[mt][f][0], accF[mt][f][1]);
                    *(uint32_t*)(gib + (size_t)rr1 * GIP + col) =
                        f2h2(accF[mt][f][2], accF[mt][f][3]);
                }
            }
            mbar_arrive(mb_full0 + 8 * buf);
        }
    }
}

extern "C" void kernel_launch(void* const* d_in, const int* in_sizes, int n_in,
                              void* d_out, int out_size) {
    const float* x     = (const float*)d_in[0];
    const int*   amask = (const int*)d_in[1];
    // d_in[2] = label: always arange(L) by construction.
    const float* Wih   = (const float*)d_in[3];
    const float* Whh   = (const float*)d_in[4];
    const float* bih   = (const float*)d_in[5];
    const float* bhh   = (const float*)d_in[6];
    float*       out   = (float*)d_out;

    cudaFuncSetAttribute(gru_fused_kernel, cudaFuncAttributeMaxDynamicSharedMemorySize,
                         SMEM_TOTAL);

    const size_t nchunks = (size_t)BATCH * SEQ * DIM / 4 + (size_t)NPAIR * G3 * DIM / 4;
    convert_kernel<<<(unsigned)((nchunks + 255) / 256), 256>>>(x, Wih);

    dim3 g(4, 32);
    gru_fused_kernel<<<g, 384, SMEM_TOTAL>>>(Whh, bih, bhh, amask, out);
}